// round 8
// baseline (speedup 1.0000x reference)
#include <cuda_runtime.h>
#include <cstdint>

#define BSZ   8
#define SSZ   512
#define HDIM  4096
#define NH    64
#define HD    64
#define MDIM  (BSZ*SSZ)
#define NHEADS (BSZ*NH)

// ---------------- scratch ----------------
__device__ float g_q[(size_t)MDIM*HDIM];
__device__ float g_k[(size_t)MDIM*HDIM];
__device__ float g_v[(size_t)MDIM*HDIM];
__device__ float g_ctx[(size_t)MDIM*HDIM];
__device__ float g_proj[(size_t)MDIM*HDIM];
__device__ float g_sp[(size_t)NHEADS*SSZ*SSZ];   // probs only
__device__ float g_act[(size_t)MDIM*HDIM];
__device__ float g_w[4][(size_t)HDIM*HDIM];
__device__ float g_maxes[8];
// 0=q 1=k 2=v 3=scores 4=probs 5=ctx 6=proj 7=final

// ---------------- helpers ----------------
__device__ __forceinline__ float scale_from_max(float m) {
    m = fmaxf(m, 1e-12f);
    return exp2f(15.0f - ceilf(log2f(m)));
}
__device__ __forceinline__ float quantv(float x, float s, float inv) {
    float r = rintf(x * s);
    r = fminf(fmaxf(r, -32768.0f), 32767.0f);
    return r * inv;
}
__device__ __forceinline__ void atomic_amax(float* a, float v) {
    atomicMax((int*)a, __float_as_int(v));
}
__device__ __forceinline__ float block_reduce_max(float v, float* sm, int nthr) {
    int t = threadIdx.x;
    sm[t] = v; __syncthreads();
    for (int off = nthr >> 1; off > 0; off >>= 1) {
        if (t < off) sm[t] = fmaxf(sm[t], sm[t + off]);
        __syncthreads();
    }
    float r = sm[0]; __syncthreads();
    return r;
}
__device__ __forceinline__ float block_reduce_sum(float v, float* sm) {
    int t = threadIdx.x;
    sm[t] = v; __syncthreads();
    for (int off = blockDim.x >> 1; off > 0; off >>= 1) {
        if (t < off) sm[t] += sm[t + off];
        __syncthreads();
    }
    float r = sm[0]; __syncthreads();
    return r;
}
__device__ __forceinline__ float f2tf32f(float x) {
    uint32_t r;
    asm("cvt.rna.tf32.f32 %0, %1;" : "=r"(r) : "f"(x));
    return __uint_as_float(r);
}
__device__ __forceinline__ void mma_tf32(
    float& c0, float& c1, float& c2, float& c3,
    uint32_t a0, uint32_t a1, uint32_t a2, uint32_t a3,
    uint32_t b0, uint32_t b1)
{
    asm volatile(
        "mma.sync.aligned.m16n8k8.row.col.f32.tf32.tf32.f32 "
        "{%0,%1,%2,%3}, {%4,%5,%6,%7}, {%8,%9}, {%0,%1,%2,%3};"
        : "+f"(c0), "+f"(c1), "+f"(c2), "+f"(c3)
        : "r"(a0), "r"(a1), "r"(a2), "r"(a3), "r"(b0), "r"(b1));
}
__device__ __forceinline__ void cp_async16(uint32_t smem_addr, const void* gptr) {
    asm volatile("cp.async.cg.shared.global [%0], [%1], 16;" :: "r"(smem_addr), "l"(gptr));
}
__device__ __forceinline__ void cp_commit() {
    asm volatile("cp.async.commit_group;" ::: "memory");
}
template<int N> __device__ __forceinline__ void cp_wait() {
    asm volatile("cp.async.wait_group %0;" :: "n"(N) : "memory");
}
__device__ __forceinline__ uint32_t ldsf(const float* p) {
    return __float_as_uint(*p);
}

__global__ void reset_kernel() {
    if (threadIdx.x < 8) g_maxes[threadIdx.x] = 0.0f;
}

// ---------------- tf32 pre-round ----------------
__global__ void rnd_kernel(const float* __restrict__ src, float* __restrict__ dst, int n4) {
    int i = blockIdx.x * blockDim.x + threadIdx.x;
    if (i < n4) {
        float4 v = ((const float4*)src)[i];
        v.x = f2tf32f(v.x); v.y = f2tf32f(v.y); v.z = f2tf32f(v.z); v.w = f2tf32f(v.w);
        ((float4*)dst)[i] = v;
    }
}

// ---------------- quantize + tf32 round (ctx before dense GEMM) ----------------
__global__ void quant_rnd_kernel(float* __restrict__ p, int n4, int maxidx) {
    float s = scale_from_max(g_maxes[maxidx]);
    float inv = 1.0f / s;
    int i = blockIdx.x * blockDim.x + threadIdx.x;
    if (i < n4) {
        float4 v = ((float4*)p)[i];
        v.x = f2tf32f(quantv(v.x, s, inv));
        v.y = f2tf32f(quantv(v.y, s, inv));
        v.z = f2tf32f(quantv(v.z, s, inv));
        v.w = f2tf32f(quantv(v.w, s, inv));
        ((float4*)p)[i] = v;
    }
}

// ---------------- plain quantize (final output) ----------------
__global__ void quant_kernel(float* __restrict__ p, int n4, int maxidx) {
    float s = scale_from_max(g_maxes[maxidx]);
    float inv = 1.0f / s;
    int i = blockIdx.x * blockDim.x + threadIdx.x;
    if (i < n4) {
        float4 v = ((float4*)p)[i];
        v.x = quantv(v.x, s, inv);
        v.y = quantv(v.y, s, inv);
        v.z = quantv(v.z, s, inv);
        v.w = quantv(v.w, s, inv);
        ((float4*)p)[i] = v;
    }
}

// ---------------- tf32 GEMM, 3-stage cp.async pipeline ----------------
#define BKT 16
#define KSTRIDE 20

__global__ __launch_bounds__(256) void gemm_tf32_kernel(
    const float* __restrict__ A, const float* __restrict__ W,
    const float* __restrict__ bias, float* __restrict__ C, int maxidx)
{
    __shared__ float As[3][128][KSTRIDE];
    __shared__ float Bs[3][128][KSTRIDE];
    __shared__ float red[256];

    const int tid   = threadIdx.x;
    const int wid   = tid >> 5;
    const int lane  = tid & 31;
    const int g     = lane >> 2;
    const int tg    = lane & 3;
    const int warp_m = wid & 1;
    const int warp_n = wid >> 1;
    const int rowBase = blockIdx.y * 128;
    const int colBase = blockIdx.x * 128;

    const int c_row0 = tid >> 2;
    const int c_seg  = (tid & 3) << 2;
    const int c_row1 = c_row0 + 64;

    float acc[4][4][4];
#pragma unroll
    for (int mt = 0; mt < 4; mt++)
#pragma unroll
        for (int nt = 0; nt < 4; nt++)
#pragma unroll
            for (int i = 0; i < 4; i++) acc[mt][nt][i] = 0.0f;

    auto issue_copy = [&](int buf, int k0) {
        const float* asrc0 = A + (size_t)(rowBase + c_row0) * 4096 + k0 + c_seg;
        const float* asrc1 = A + (size_t)(rowBase + c_row1) * 4096 + k0 + c_seg;
        const float* bsrc0 = W + (size_t)(colBase + c_row0) * 4096 + k0 + c_seg;
        const float* bsrc1 = W + (size_t)(colBase + c_row1) * 4096 + k0 + c_seg;
        cp_async16((uint32_t)__cvta_generic_to_shared(&As[buf][c_row0][c_seg]), asrc0);
        cp_async16((uint32_t)__cvta_generic_to_shared(&As[buf][c_row1][c_seg]), asrc1);
        cp_async16((uint32_t)__cvta_generic_to_shared(&Bs[buf][c_row0][c_seg]), bsrc0);
        cp_async16((uint32_t)__cvta_generic_to_shared(&Bs[buf][c_row1][c_seg]), bsrc1);
        cp_commit();
    };

    const int NITER = 4096 / BKT;   // 256
    issue_copy(0, 0);
    issue_copy(1, BKT);

    for (int iter = 0; iter < NITER; iter++) {
        const int buf = iter % 3;
        if (iter + 2 < NITER) {
            issue_copy((iter + 2) % 3, (iter + 2) * BKT);
            cp_wait<2>();
        } else if (iter + 2 == NITER) {
            cp_wait<1>();
        } else {
            cp_wait<0>();
        }
        __syncthreads();

#pragma unroll
        for (int ks = 0; ks < 2; ks++) {
            const int kb = ks * 8;
            uint32_t af[4][4];
#pragma unroll
            for (int mt = 0; mt < 4; mt++) {
                const int m = warp_m * 64 + mt * 16 + g;
                af[mt][0] = ldsf(&As[buf][m    ][kb + tg]);
                af[mt][1] = ldsf(&As[buf][m + 8][kb + tg]);
                af[mt][2] = ldsf(&As[buf][m    ][kb + tg + 4]);
                af[mt][3] = ldsf(&As[buf][m + 8][kb + tg + 4]);
            }
            uint32_t bf[4][2];
#pragma unroll
            for (int nt = 0; nt < 4; nt++) {
                const int n = warp_n * 32 + nt * 8 + g;
                bf[nt][0] = ldsf(&Bs[buf][n][kb + tg]);
                bf[nt][1] = ldsf(&Bs[buf][n][kb + tg + 4]);
            }
#pragma unroll
            for (int mt = 0; mt < 4; mt++)
#pragma unroll
                for (int nt = 0; nt < 4; nt++)
                    mma_tf32(acc[mt][nt][0], acc[mt][nt][1], acc[mt][nt][2], acc[mt][nt][3],
                             af[mt][0], af[mt][1], af[mt][2], af[mt][3],
                             bf[nt][0], bf[nt][1]);
        }
        __syncthreads();
    }

    float amax = 0.0f;
#pragma unroll
    for (int mt = 0; mt < 4; mt++) {
        const int row0 = rowBase + warp_m * 64 + mt * 16 + g;
#pragma unroll
        for (int nt = 0; nt < 4; nt++) {
            const int col = colBase + warp_n * 32 + nt * 8 + tg * 2;
            const float b0 = bias[col], b1 = bias[col + 1];
            float v0 = acc[mt][nt][0] + b0;
            float v1 = acc[mt][nt][1] + b1;
            float v2 = acc[mt][nt][2] + b0;
            float v3 = acc[mt][nt][3] + b1;
            *(float2*)(C + (size_t)row0 * 4096 + col)       = make_float2(v0, v1);
            *(float2*)(C + (size_t)(row0 + 8) * 4096 + col) = make_float2(v2, v3);
            amax = fmaxf(amax, fmaxf(fmaxf(fabsf(v0), fabsf(v1)), fmaxf(fabsf(v2), fabsf(v3))));
        }
    }
    amax = block_reduce_max(amax, red, 256);
    if (tid == 0) atomic_amax(&g_maxes[maxidx], amax);
}

// ---------------- Pass A: scores amax only (no stores), fused q/k quant ----------------
// grid (4,4,512); block 256; tile 128x128, K=64.
#define SSTRIDE 68
#define SS_SMEM (2 * 128 * SSTRIDE * 4)

__global__ __launch_bounds__(256) void scores_amax_kernel() {
    extern __shared__ float sm[];
    float* Qs = sm;                      // [128][68]
    float* Ks = sm + 128 * SSTRIDE;      // [128][68]
    __shared__ float red[256];

    const int head = blockIdx.z;
    const int b = head >> 6, n = head & 63;
    const int i0 = blockIdx.x * 128, j0 = blockIdx.y * 128;
    const float* qb = g_q + (size_t)(b * 512 + i0) * 4096 + n * 64;
    const float* kb = g_k + (size_t)(b * 512 + j0) * 4096 + n * 64;

    const int tid  = threadIdx.x;
    const int wid  = tid >> 5;
    const int lane = tid & 31;
    const int g    = lane >> 2;
    const int tg   = lane & 3;
    const int warp_m = wid & 1;
    const int warp_n = wid >> 1;

    const float s0 = scale_from_max(g_maxes[0]), inv0 = 1.0f / s0;
    const float s1 = scale_from_max(g_maxes[1]), inv1 = 1.0f / s1;

#pragma unroll
    for (int it = 0; it < 8; it++) {
        int id = tid + it * 256;         // 0..2047
        int r  = id >> 4;                // 0..127
        int c  = (id & 15) << 2;
        float4 qv = *(const float4*)(qb + (size_t)r * 4096 + c);
        Qs[r * SSTRIDE + c + 0] = f2tf32f(quantv(qv.x, s0, inv0));
        Qs[r * SSTRIDE + c + 1] = f2tf32f(quantv(qv.y, s0, inv0));
        Qs[r * SSTRIDE + c + 2] = f2tf32f(quantv(qv.z, s0, inv0));
        Qs[r * SSTRIDE + c + 3] = f2tf32f(quantv(qv.w, s0, inv0));
        float4 kv = *(const float4*)(kb + (size_t)r * 4096 + c);
        Ks[r * SSTRIDE + c + 0] = f2tf32f(quantv(kv.x, s1, inv1));
        Ks[r * SSTRIDE + c + 1] = f2tf32f(quantv(kv.y, s1, inv1));
        Ks[r * SSTRIDE + c + 2] = f2tf32f(quantv(kv.z, s1, inv1));
        Ks[r * SSTRIDE + c + 3] = f2tf32f(quantv(kv.w, s1, inv1));
    }
    __syncthreads();

    float acc[4][4][4];
#pragma unroll
    for (int mt = 0; mt < 4; mt++)
#pragma unroll
        for (int nt = 0; nt < 4; nt++)
#pragma unroll
            for (int i = 0; i < 4; i++) acc[mt][nt][i] = 0.0f;

#pragma unroll
    for (int ks = 0; ks < 8; ks++) {
        const int kbase = ks * 8;
        uint32_t af[4][4];
#pragma unroll
        for (int mt = 0; mt < 4; mt++) {
            const int m = warp_m * 64 + mt * 16 + g;
            af[mt][0] = ldsf(&Qs[(m    ) * SSTRIDE + kbase + tg]);
            af[mt][1] = ldsf(&Qs[(m + 8) * SSTRIDE + kbase + tg]);
            af[mt][2] = ldsf(&Qs[(m    ) * SSTRIDE + kbase + tg + 4]);
            af[mt][3] = ldsf(&Qs[(m + 8) * SSTRIDE + kbase + tg + 4]);
        }
        uint32_t bf[4][2];
#pragma unroll
        for (int nt = 0; nt < 4; nt++) {
            const int nn = warp_n * 32 + nt * 8 + g;
            bf[nt][0] = ldsf(&Ks[nn * SSTRIDE + kbase + tg]);
            bf[nt][1] = ldsf(&Ks[nn * SSTRIDE + kbase + tg + 4]);
        }
#pragma unroll
        for (int mt = 0; mt < 4; mt++)
#pragma unroll
            for (int nt = 0; nt < 4; nt++)
                mma_tf32(acc[mt][nt][0], acc[mt][nt][1], acc[mt][nt][2], acc[mt][nt][3],
                         af[mt][0], af[mt][1], af[mt][2], af[mt][3],
                         bf[nt][0], bf[nt][1]);
    }

    float amax = 0.0f;
#pragma unroll
    for (int mt = 0; mt < 4; mt++)
#pragma unroll
        for (int nt = 0; nt < 4; nt++)
#pragma unroll
            for (int i = 0; i < 4; i++)
                amax = fmaxf(amax, fabsf(acc[mt][nt][i] * 0.125f));
    amax = block_reduce_max(amax, red, 256);
    if (tid == 0) atomic_amax(&g_maxes[3], amax);
}

// ---------------- Pass B: recompute scores + quant + mask + softmax -> probs ----------------
// grid (8, 512): 64-row i-tile per block; j streamed in 4 chunks of 128.
#define FS_QS  0
#define FS_KS  (64 * SSTRIDE)                       // 4352
#define FS_SC  (64 * SSTRIDE + 128 * SSTRIDE)       // 13056
#define SCST   516
#define FS_SMEM ((64 * SSTRIDE + 128 * SSTRIDE + 64 * SCST) * 4)

__global__ __launch_bounds__(256) void softmax_fused_kernel(const float* __restrict__ mask) {
    extern __shared__ float sm[];
    float* Qs = sm + FS_QS;     // [64][68]
    float* Ks = sm + FS_KS;     // [128][68]
    float* Sc = sm + FS_SC;     // [64][516]
    __shared__ float red8[8];

    const int head = blockIdx.y;
    const int b = head >> 6, n = head & 63;
    const int i0 = blockIdx.x * 64;
    const int tid  = threadIdx.x;
    const int wid  = tid >> 5;
    const int lane = tid & 31;
    const int g    = lane >> 2;
    const int tg   = lane & 3;
    const int warp_m = wid & 1;     // 2 x 32 rows
    const int warp_n = wid >> 1;    // 4 x 32 cols

    const float s0 = scale_from_max(g_maxes[0]), inv0 = 1.0f / s0;
    const float s1 = scale_from_max(g_maxes[1]), inv1 = 1.0f / s1;
    const float s3 = scale_from_max(g_maxes[3]), inv3 = 1.0f / s3;
    const float* mrow = mask + (size_t)b * 512;

    // load Q tile 64x64 with quant+rnd
    const float* qb = g_q + (size_t)(b * 512 + i0) * 4096 + n * 64;
#pragma unroll
    for (int it = 0; it < 4; it++) {
        int id = tid + it * 256;        // 0..1023
        int r  = id >> 4;               // 0..63
        int c  = (id & 15) << 2;
        float4 qv = *(const float4*)(qb + (size_t)r * 4096 + c);
        Qs[r * SSTRIDE + c + 0] = f2tf32f(quantv(qv.x, s0, inv0));
        Qs[r * SSTRIDE + c + 1] = f2tf32f(quantv(qv.y, s0, inv0));
        Qs[r * SSTRIDE + c + 2] = f2tf32f(quantv(qv.z, s0, inv0));
        Qs[r * SSTRIDE + c + 3] = f2tf32f(quantv(qv.w, s0, inv0));
    }

    const float* kbase_p = g_k + (size_t)(b * 512) * 4096 + n * 64;
    for (int j0 = 0; j0 < 512; j0 += 128) {
        // load K chunk 128x64 with quant+rnd
#pragma unroll
        for (int it = 0; it < 8; it++) {
            int id = tid + it * 256;    // 0..2047
            int r  = id >> 4;           // 0..127
            int c  = (id & 15) << 2;
            float4 kv = *(const float4*)(kbase_p + (size_t)(j0 + r) * 4096 + c);
            Ks[r * SSTRIDE + c + 0] = f2tf32f(quantv(kv.x, s1, inv1));
            Ks[r * SSTRIDE + c + 1] = f2tf32f(quantv(kv.y, s1, inv1));
            Ks[r * SSTRIDE + c + 2] = f2tf32f(quantv(kv.z, s1, inv1));
            Ks[r * SSTRIDE + c + 3] = f2tf32f(quantv(kv.w, s1, inv1));
        }
        __syncthreads();

        float acc[2][4][4];
#pragma unroll
        for (int mt = 0; mt < 2; mt++)
#pragma unroll
            for (int nt = 0; nt < 4; nt++)
#pragma unroll
                for (int i = 0; i < 4; i++) acc[mt][nt][i] = 0.0f;

#pragma unroll
        for (int ks = 0; ks < 8; ks++) {
            const int kbs = ks * 8;
            uint32_t af[2][4];
#pragma unroll
            for (int mt = 0; mt < 2; mt++) {
                const int m = warp_m * 32 + mt * 16 + g;
                af[mt][0] = ldsf(&Qs[(m    ) * SSTRIDE + kbs + tg]);
                af[mt][1] = ldsf(&Qs[(m + 8) * SSTRIDE + kbs + tg]);
                af[mt][2] = ldsf(&Qs[(m    ) * SSTRIDE + kbs + tg + 4]);
                af[mt][3] = ldsf(&Qs[(m + 8) * SSTRIDE + kbs + tg + 4]);
            }
            uint32_t bf[4][2];
#pragma unroll
            for (int nt = 0; nt < 4; nt++) {
                const int nn = warp_n * 32 + nt * 8 + g;
                bf[nt][0] = ldsf(&Ks[nn * SSTRIDE + kbs + tg]);
                bf[nt][1] = ldsf(&Ks[nn * SSTRIDE + kbs + tg + 4]);
            }
#pragma unroll
            for (int mt = 0; mt < 2; mt++)
#pragma unroll
                for (int nt = 0; nt < 4; nt++)
                    mma_tf32(acc[mt][nt][0], acc[mt][nt][1], acc[mt][nt][2], acc[mt][nt][3],
                             af[mt][0], af[mt][1], af[mt][2], af[mt][3],
                             bf[nt][0], bf[nt][1]);
        }

        // epilogue: scale + quant + mask into Sc
#pragma unroll
        for (int mt = 0; mt < 2; mt++) {
            const int row0 = warp_m * 32 + mt * 16 + g;
#pragma unroll
            for (int nt = 0; nt < 4; nt++) {
                const int col = warp_n * 32 + nt * 8 + tg * 2;
                const int jg = j0 + col;
                const float m0 = mrow[jg], m1 = mrow[jg + 1];
                float2 w0, w1;
                w0.x = quantv(acc[mt][nt][0] * 0.125f, s3, inv3) + m0;
                w0.y = quantv(acc[mt][nt][1] * 0.125f, s3, inv3) + m1;
                w1.x = quantv(acc[mt][nt][2] * 0.125f, s3, inv3) + m0;
                w1.y = quantv(acc[mt][nt][3] * 0.125f, s3, inv3) + m1;
                *(float2*)&Sc[(size_t)row0 * SCST + jg]       = w0;
                *(float2*)&Sc[(size_t)(row0 + 8) * SCST + jg] = w1;
            }
        }
        __syncthreads();
    }

    // softmax: warp w handles rows w*8 .. w*8+7
    float pamax = 0.0f;
    float* pbase = g_sp + ((size_t)head * 512 + i0) * 512;
    for (int r8 = 0; r8 < 8; r8++) {
        const int row = wid * 8 + r8;
        float vals[16];
        float mx = -1e30f;
#pragma unroll
        for (int u = 0; u < 4; u++) {
            float4 vv = *(float4*)&Sc[(size_t)row * SCST + u * 128 + lane * 4];
            vals[u * 4 + 0] = vv.x; vals[u * 4 + 1] = vv.y;
            vals[u * 4 + 2] = vv.z; vals[u * 4 + 3] = vv.w;
            mx = fmaxf(mx, fmaxf(fmaxf(vv.x, vv.y), fmaxf(vv.z, vv.w)));
        }
#pragma unroll
        for (int off = 16; off > 0; off >>= 1)
            mx = fmaxf(mx, __shfl_xor_sync(0xffffffffu, mx, off));
        float sum = 0.0f;
#pragma unroll
        for (int u = 0; u < 16; u++) { vals[u] = expf(vals[u] - mx); sum += vals[u]; }
#pragma unroll
        for (int off = 16; off > 0; off >>= 1)
            sum += __shfl_xor_sync(0xffffffffu, sum, off);
        const float rs = 1.0f / sum;
#pragma unroll
        for (int u = 0; u < 4; u++) {
            float4 p;
            p.x = vals[u * 4 + 0] * rs;
            p.y = vals[u * 4 + 1] * rs;
            p.z = vals[u * 4 + 2] * rs;
            p.w = vals[u * 4 + 3] * rs;
            pamax = fmaxf(pamax, fmaxf(fmaxf(p.x, p.y), fmaxf(p.z, p.w)));
            *(float4*)(pbase + (size_t)row * 512 + u * 128 + lane * 4) = p;
        }
    }
#pragma unroll
    for (int off = 16; off > 0; off >>= 1)
        pamax = fmaxf(pamax, __shfl_xor_sync(0xffffffffu, pamax, off));
    if (lane == 0) red8[wid] = pamax;
    __syncthreads();
    if (tid == 0) {
        float m = red8[0];
#pragma unroll
        for (int w = 1; w < 8; w++) m = fmaxf(m, red8[w]);
        atomic_amax(&g_maxes[4], m);
    }
}

// ---------------- ctx = quant(probs) @ quant(v) per head (tf32 mma) ----------------
#define CS_SMEM ((128 * SSTRIDE + 64 * SSTRIDE) * 4)

__global__ __launch_bounds__(256) void ctx_mma_kernel() {
    extern __shared__ float sm[];
    float* Ps = sm;                      // [128 i][68 j]
    float* Vs = sm + 128 * SSTRIDE;      // [64 d][68 j]
    __shared__ float red[256];

    const int head = blockIdx.y;
    const int b = head >> 6, n = head & 63;
    const int i0 = blockIdx.x * 128;
    const int tid  = threadIdx.x;
    const int wid  = tid >> 5;
    const int lane = tid & 31;
    const int g    = lane >> 2;
    const int tg   = lane & 3;
    const int warp_m = wid & 3;
    const int warp_n = wid >> 2;

    const float s4 = scale_from_max(g_maxes[4]), inv4 = 1.0f / s4;
    const float s2 = scale_from_max(g_maxes[2]), inv2 = 1.0f / s2;

    float acc[2][4][4];
#pragma unroll
    for (int mt = 0; mt < 2; mt++)
#pragma unroll
        for (int nt = 0; nt < 4; nt++)
#pragma unroll
            for (int i = 0; i < 4; i++) acc[mt][nt][i] = 0.0f;

    const float* pb = g_sp + ((size_t)head * 512 + i0) * 512;
    const float* vb = g_v + (size_t)(b * 512) * 4096 + n * 64;

    for (int j0 = 0; j0 < 512; j0 += 64) {
#pragma unroll
        for (int it = 0; it < 8; it++) {
            int id = tid + it * 256;
            int r  = id >> 4;
            int c  = (id & 15) << 2;
            float4 pv = *(const float4*)(pb + (size_t)r * 512 + j0 + c);
            Ps[r * SSTRIDE + c + 0] = f2tf32f(quantv(pv.x, s4, inv4));
            Ps[r * SSTRIDE + c + 1] = f2tf32f(quantv(pv.y, s4, inv4));
            Ps[r * SSTRIDE + c + 2] = f2tf32f(quantv(pv.z, s4, inv4));
            Ps[r * SSTRIDE + c + 3] = f2tf32f(quantv(pv.w, s4, inv4));
        }
#pragma unroll
        for (int it = 0; it < 4; it++) {
            int id = tid + it * 256;
            int r  = id >> 4;
            int c  = (id & 15) << 2;
            float4 vv = *(const float4*)(vb + (size_t)(j0 + r) * 4096 + c);
            Vs[(c + 0) * SSTRIDE + r] = f2tf32f(quantv(vv.x, s2, inv2));
            Vs[(c + 1) * SSTRIDE + r] = f2tf32f(quantv(vv.y, s2, inv2));
            Vs[(c + 2) * SSTRIDE + r] = f2tf32f(quantv(vv.z, s2, inv2));
            Vs[(c + 3) * SSTRIDE + r] = f2tf32f(quantv(vv.w, s2, inv2));
        }
        __syncthreads();

#pragma unroll
        for (int ks = 0; ks < 8; ks++) {
            const int kbase = ks * 8;
            uint32_t af[2][4];
#pragma unroll
            for (int mt = 0; mt < 2; mt++) {
                const int m = warp_m * 32 + mt * 16 + g;
                af[mt][0] = ldsf(&Ps[(m    ) * SSTRIDE + kbase + tg]);
                af[mt][1] = ldsf(&Ps[(m + 8) * SSTRIDE + kbase + tg]);
                af[mt][2] = ldsf(&Ps[(m    ) * SSTRIDE + kbase + tg + 4]);
                af[mt][3] = ldsf(&Ps[(m + 8) * SSTRIDE + kbase + tg + 4]);
            }
            uint32_t bf[4][2];
#pragma unroll
            for (int nt = 0; nt < 4; nt++) {
                const int nn = warp_n * 32 + nt * 8 + g;
                bf[nt][0] = ldsf(&Vs[nn * SSTRIDE + kbase + tg]);
                bf[nt][1] = ldsf(&Vs[nn * SSTRIDE + kbase + tg + 4]);
            }
#pragma unroll
            for (int mt = 0; mt < 2; mt++)
#pragma unroll
                for (int nt = 0; nt < 4; nt++)
                    mma_tf32(acc[mt][nt][0], acc[mt][nt][1], acc[mt][nt][2], acc[mt][nt][3],
                             af[mt][0], af[mt][1], af[mt][2], af[mt][3],
                             bf[nt][0], bf[nt][1]);
        }
        __syncthreads();
    }

    float amax = 0.0f;
#pragma unroll
    for (int mt = 0; mt < 2; mt++) {
        const int row0 = i0 + warp_m * 32 + mt * 16 + g;
#pragma unroll
        for (int nt = 0; nt < 4; nt++) {
            const int col = warp_n * 32 + nt * 8 + tg * 2;
            float* c0 = g_ctx + (size_t)(b * 512 + row0) * 4096 + n * 64 + col;
            float* c1 = g_ctx + (size_t)(b * 512 + row0 + 8) * 4096 + n * 64 + col;
            *(float2*)c0 = make_float2(acc[mt][nt][0], acc[mt][nt][1]);
            *(float2*)c1 = make_float2(acc[mt][nt][2], acc[mt][nt][3]);
            amax = fmaxf(amax, fmaxf(fmaxf(fabsf(acc[mt][nt][0]), fabsf(acc[mt][nt][1])),
                                     fmaxf(fabsf(acc[mt][nt][2]), fabsf(acc[mt][nt][3]))));
        }
    }
    amax = block_reduce_max(amax, red, 256);
    if (tid == 0) atomic_amax(&g_maxes[5], amax);
}

// ---------------- quant(proj) + residual + LayerNorm ----------------
__global__ __launch_bounds__(256) void ln_kernel(
    const float* __restrict__ x, const float* __restrict__ lnw,
    const float* __restrict__ lnb, float* __restrict__ out)
{
    __shared__ float ybuf[4096];
    __shared__ float red[256];
    const int r = blockIdx.x;
    const int tid = threadIdx.x;
    const float s6 = scale_from_max(g_maxes[6]);
    const float inv6 = 1.0f / s6;
    const float* xr = x + (size_t)r * 4096;
    const float* pr = g_proj + (size_t)r * 4096;

    float sum = 0.0f;
    for (int i = tid; i < 4096; i += 256) {
        float y = xr[i] + quantv(pr[i], s6, inv6);
        ybuf[i] = y;
        sum += y;
    }
    sum = block_reduce_sum(sum, red);
    const float mu = sum * (1.0f / 4096.0f);

    float s2 = 0.0f;
    for (int i = tid; i < 4096; i += 256) {
        float d = ybuf[i] - mu;
        s2 += d * d;
    }
    s2 = block_reduce_sum(s2, red);
    const float var = s2 * (1.0f / 4096.0f);
    const float rinv = rsqrtf(var + 1e-12f);

    float amax = 0.0f;
    float* orow = out + (size_t)r * 4096;
    for (int i = tid; i < 4096; i += 256) {
        float o = (ybuf[i] - mu) * rinv * lnw[i] + lnb[i];
        orow[i] = o;
        amax = fmaxf(amax, fabsf(o));
    }
    amax = block_reduce_max(amax, red, 256);
    if (tid == 0) atomic_amax(&g_maxes[7], amax);
}

// ---------------- launch ----------------
static void* sym_addr(const void* sym) {
    void* p = nullptr;
    cudaGetSymbolAddress(&p, sym);
    return p;
}

extern "C" void kernel_launch(void* const* d_in, const int* in_sizes, int n_in,
                              void* d_out, int out_size)
{
    (void)in_sizes; (void)n_in; (void)out_size;
    const float* x    = (const float*)d_in[0];
    const float* mask = (const float*)d_in[1];
    const float* Wq   = (const float*)d_in[2];
    const float* bq   = (const float*)d_in[3];
    const float* Wk   = (const float*)d_in[4];
    const float* bk   = (const float*)d_in[5];
    const float* Wv   = (const float*)d_in[6];
    const float* bv   = (const float*)d_in[7];
    const float* Wd   = (const float*)d_in[8];
    const float* bd   = (const float*)d_in[9];
    const float* lnw  = (const float*)d_in[10];
    const float* lnb  = (const float*)d_in[11];
    float* out = (float*)d_out;

    float* q    = (float*)sym_addr(g_q);
    float* k    = (float*)sym_addr(g_k);
    float* v    = (float*)sym_addr(g_v);
    float* ctx  = (float*)sym_addr(g_ctx);
    float* proj = (float*)sym_addr(g_proj);
    float* act  = (float*)sym_addr(g_act);
    float* w    = (float*)sym_addr(g_w);
    const size_t WSZ = (size_t)HDIM * HDIM;

    static int smem_set = 0;
    if (!smem_set) {
        cudaFuncSetAttribute(scores_amax_kernel,
                             cudaFuncAttributeMaxDynamicSharedMemorySize, SS_SMEM);
        cudaFuncSetAttribute(softmax_fused_kernel,
                             cudaFuncAttributeMaxDynamicSharedMemorySize, FS_SMEM);
        cudaFuncSetAttribute(ctx_mma_kernel,
                             cudaFuncAttributeMaxDynamicSharedMemorySize, CS_SMEM);
        smem_set = 1;
    }

    const int n4 = (MDIM * HDIM) / 4;
    const int qblocks = n4 / 256;

    reset_kernel<<<1, 32>>>();

    rnd_kernel<<<qblocks, 256>>>(x,  act, n4);
    rnd_kernel<<<qblocks, 256>>>(Wq, w + 0 * WSZ, n4);
    rnd_kernel<<<qblocks, 256>>>(Wk, w + 1 * WSZ, n4);
    rnd_kernel<<<qblocks, 256>>>(Wv, w + 2 * WSZ, n4);
    rnd_kernel<<<qblocks, 256>>>(Wd, w + 3 * WSZ, n4);

    dim3 gg(32, 32);
    gemm_tf32_kernel<<<gg, 256>>>(act, w + 0 * WSZ, bq, q, 0);
    gemm_tf32_kernel<<<gg, 256>>>(act, w + 1 * WSZ, bk, k, 1);
    gemm_tf32_kernel<<<gg, 256>>>(act, w + 2 * WSZ, bv, v, 2);

    scores_amax_kernel<<<dim3(4, 4, 512), 256, SS_SMEM>>>();
    softmax_fused_kernel<<<dim3(8, 512), 256, FS_SMEM>>>(mask);
    ctx_mma_kernel<<<dim3(4, 512), 256, CS_SMEM>>>();

    quant_rnd_kernel<<<qblocks, 256>>>(ctx, n4, 5);

    gemm_tf32_kernel<<<gg, 256>>>(ctx, w + 3 * WSZ, bd, proj, 6);

    ln_kernel<<<MDIM, 256>>>(x, lnw, lnb, out);
    quant_kernel<<<qblocks, 256>>>(out, n4, 7);
}